// round 1
// baseline (speedup 1.0000x reference)
#include <cuda_runtime.h>
#include <cstdint>

#define FULLMASK 0xffffffffu

// ---------------------------------------------------------------------------
// Problem constants (shapes fixed by the dataset)
//   query: [65536, 256] (b*s*h flattened), c_keys/c_prime_keys: [1024, 128]
// ---------------------------------------------------------------------------
#define R_TOT 65536
#define D_DIM 256
#define SUB   128
#define N_C   1024

// 512 MB scratch for the full score matrix [R_TOT][2048] (half0 | half1)
__device__ float g_scores[(size_t)R_TOT * 2048];

// ---------------------------------------------------------------------------
// Joint candidate table: all (i,j) with (i+1)*(j+1) <= 16  (50 cells).
// Any other joint cell has >=16 dominators (sum >=, smaller flat idx on ties)
// so it can never be in the final top-16.
// ---------------------------------------------------------------------------
__constant__ unsigned char c_CI[50] = {
    0,0,0,0,0,0,0,0,0,0,0,0,0,0,0,0,
    1,1,1,1,1,1,1,1,
    2,2,2,2,2,
    3,3,3,3,
    4,4,4,
    5,5,
    6,6,
    7,7,
    8,9,10,11,12,13,14,15
};
__constant__ unsigned char c_CJ[50] = {
    0,1,2,3,4,5,6,7,8,9,10,11,12,13,14,15,
    0,1,2,3,4,5,6,7,
    0,1,2,3,4,
    0,1,2,3,
    0,1,2,
    0,1,
    0,1,
    0,1,
    0,0,0,0,0,0,0,0
};

// Monotonic float <-> uint mapping (order-preserving over all finite floats)
__device__ __forceinline__ unsigned fmono(float f) {
    unsigned u = __float_as_uint(f);
    return u ^ (unsigned)(((int)u >> 31) | (int)0x80000000);
}
__device__ __forceinline__ float funmono(unsigned m) {
    return __uint_as_float((m & 0x80000000u) ? (m ^ 0x80000000u) : ~m);
}

// ---------------------------------------------------------------------------
// Kernel 1: fused LayerNorm + dual score GEMM.
//   Block: 256 threads, TM=32 rows, loops over 16 tiles of 128 centroids
//   (8 tiles * 2 halves). Keys tile staged k-major in smem; 4x4 microtile.
// ---------------------------------------------------------------------------
#define KS_STRIDE 132   // padded col stride for transposed keys tile

__global__ __launch_bounds__(256, 2)
void pkr_gemm(const float* __restrict__ query,
              const float* __restrict__ ckeys,
              const float* __restrict__ cpkeys,
              const float* __restrict__ gma,
              const float* __restrict__ bta)
{
    extern __shared__ float sm[];
    float* qs = sm;               // [32][256] normalized q
    float* ks = sm + 32 * 256;    // [128 k][132] keys tile (k-major)

    const int tid = threadIdx.x;
    const int rowBase = blockIdx.x * 32;

    // ---- LayerNorm: 8 threads per row, each owns 8 float4 (32 floats) ----
    {
        const int r = tid >> 3, g = tid & 7;
        const float4* qp = (const float4*)(query + (size_t)(rowBase + r) * D_DIM);
        float4 v[8];
        float s = 0.f;
#pragma unroll
        for (int j = 0; j < 8; j++) {
            v[j] = qp[j * 8 + g];
            s += (v[j].x + v[j].y) + (v[j].z + v[j].w);
        }
#pragma unroll
        for (int off = 4; off >= 1; off >>= 1)
            s += __shfl_xor_sync(FULLMASK, s, off, 8);
        const float mu = s * (1.f / 256.f);

        float s2 = 0.f;
#pragma unroll
        for (int j = 0; j < 8; j++) {
            float dx = v[j].x - mu, dy = v[j].y - mu;
            float dz = v[j].z - mu, dw = v[j].w - mu;
            s2 += (dx * dx + dy * dy) + (dz * dz + dw * dw);
        }
#pragma unroll
        for (int off = 4; off >= 1; off >>= 1)
            s2 += __shfl_xor_sync(FULLMASK, s2, off, 8);

        const float varp = s2 * (1.f / 256.f) + 1e-5f;
        float rs = rsqrtf(varp);
        rs = rs * (1.5f - 0.5f * varp * rs * rs);  // Newton refine to ~fp32

#pragma unroll
        for (int j = 0; j < 8; j++) {
            const int c = j * 32 + g * 4;
            float* d = qs + r * 256 + c;
            d[0] = (v[j].x - mu) * rs * gma[c + 0] + bta[c + 0];
            d[1] = (v[j].y - mu) * rs * gma[c + 1] + bta[c + 1];
            d[2] = (v[j].z - mu) * rs * gma[c + 2] + bta[c + 2];
            d[3] = (v[j].w - mu) * rs * gma[c + 3] + bta[c + 3];
        }
    }
    __syncthreads();

    const int tr = tid >> 5;   // warp id -> 4-row group
    const int tc = tid & 31;   // lane -> 4-col group

    for (int tile = 0; tile < 16; ++tile) {
        const int half = tile >> 3, tn = tile & 7;
        const float4* kb = (const float4*)((half ? cpkeys : ckeys)
                                           + (size_t)tn * 128 * SUB);
        // stage keys tile transposed: ks[k][col]
#pragma unroll
        for (int i = 0; i < 16; i++) {
            int f = i * 256 + tid;          // float4 index within tile
            int k4 = f & 31, col = f >> 5;
            float4 kv = kb[col * 32 + k4];
            float* d = ks + (k4 * 4) * KS_STRIDE + col;
            d[0 * KS_STRIDE] = kv.x;
            d[1 * KS_STRIDE] = kv.y;
            d[2 * KS_STRIDE] = kv.z;
            d[3 * KS_STRIDE] = kv.w;
        }
        __syncthreads();

        float acc[4][4];
#pragma unroll
        for (int i = 0; i < 4; i++)
#pragma unroll
            for (int j = 0; j < 4; j++) acc[i][j] = 0.f;

        const float* qb = qs + (4 * tr) * 256 + half * SUB;

#pragma unroll 4
        for (int k = 0; k < 128; k += 4) {
            float kr[4][4];
#pragma unroll
            for (int kk = 0; kk < 4; kk++) {
                float4 t = *(const float4*)(ks + (k + kk) * KS_STRIDE + tc * 4);
                kr[kk][0] = t.x; kr[kk][1] = t.y; kr[kk][2] = t.z; kr[kk][3] = t.w;
            }
            float qr[4][4];
#pragma unroll
            for (int i = 0; i < 4; i++) {
                float4 t = *(const float4*)(qb + i * 256 + k);
                qr[i][0] = t.x; qr[i][1] = t.y; qr[i][2] = t.z; qr[i][3] = t.w;
            }
#pragma unroll
            for (int i = 0; i < 4; i++)
#pragma unroll
                for (int kk = 0; kk < 4; kk++)
#pragma unroll
                    for (int j = 0; j < 4; j++)
                        acc[i][j] = fmaf(qr[i][kk], kr[kk][j], acc[i][j]);
        }

        float* ob = g_scores + (size_t)(rowBase + 4 * tr) * 2048
                  + half * 1024 + tn * 128 + tc * 4;
#pragma unroll
        for (int i = 0; i < 4; i++) {
            float4 t = make_float4(acc[i][0], acc[i][1], acc[i][2], acc[i][3]);
            *(float4*)(ob + (size_t)i * 2048) = t;
        }
        __syncthreads();
    }
}

// ---------------------------------------------------------------------------
// Kernel 2: per-row exact top-16 per half (desc score, asc index ties) via
// a warp-distributed sorted list with threshold filter, then 50-candidate
// joint top-16. One warp per row.
// ---------------------------------------------------------------------------
__global__ __launch_bounds__(256)
void pkr_select(float* __restrict__ out, int Rtot)
{
    const int lane = threadIdx.x & 31;
    const int row  = blockIdx.x * 8 + (threadIdx.x >> 5);
    if (row >= Rtot) return;  // warp-uniform (R divisible by 8)

    const float* sp = g_scores + (size_t)row * 2048;

    float scH[2];
    int   eH[2];

#pragma unroll
    for (int h = 0; h < 2; h++) {
        // load 1024 scores: lane owns elements e = q*128 + lane*4 + t
        float4 sv[8];
        const float4* bp = (const float4*)(sp + h * 1024);
#pragma unroll
        for (int q2 = 0; q2 < 8; q2++) sv[q2] = bp[q2 * 32 + lane];

        // distributed top-16: lane l (l<16) holds rank-l key; key =
        // (mono(score)<<32) | (1023 - idx)  -> max-order == (score desc, idx asc)
        unsigned long long rk  = 0ull;
        unsigned long long T16 = 0ull;
        const int lbase = 1023 - lane * 4;

#pragma unroll
        for (int q2 = 0; q2 < 8; q2++) {
            const float* vv = (const float*)&sv[q2];
#pragma unroll
            for (int t = 0; t < 4; t++) {
                unsigned long long K =
                    ((unsigned long long)fmono(vv[t]) << 32)
                    | (unsigned)(lbase - q2 * 128 - t);
                unsigned bal = __ballot_sync(FULLMASK, K > T16);
                while (bal) {
                    int src = __ffs(bal) - 1;
                    bal &= bal - 1;
                    unsigned long long Kc = __shfl_sync(FULLMASK, K, src);
                    unsigned mg = __ballot_sync(FULLMASK, (lane < 16) && (Kc > rk));
                    if (mg) {
                        int pos = __ffs(mg) - 1;
                        unsigned long long up = __shfl_up_sync(FULLMASK, rk, 1);
                        if (lane >= pos && lane < 16)
                            rk = (lane == pos) ? Kc : up;
                    }
                    T16 = __shfl_sync(FULLMASK, rk, 15);
                }
            }
        }
        eH[h]  = 1023 - (int)(unsigned)rk;          // original centroid index
        scH[h] = funmono((unsigned)(rk >> 32));     // exact score bits
    }

    // ---- joint: 50 candidates (i+1)(j+1)<=16; key adds flat-idx tiebreak ----
    const float s1c = scH[0], s2c = scH[1];
    const int   e1v = eH[0],  e2v = eH[1];

    const int i0 = c_CI[lane], j0 = c_CJ[lane];
    const int cid1 = lane + 32;
    const bool v1 = (cid1 < 50);
    const int i1 = c_CI[v1 ? cid1 : 0], j1 = c_CJ[v1 ? cid1 : 0];

    const float a0 = __shfl_sync(FULLMASK, s1c, i0);
    const float b0 = __shfl_sync(FULLMASK, s2c, j0);
    const float a1 = __shfl_sync(FULLMASK, s1c, i1);
    const float b1 = __shfl_sync(FULLMASK, s2c, j1);

    unsigned long long K0 =
        ((unsigned long long)fmono(a0 + b0) << 32) | (unsigned)(4095 - (i0 * 64 + j0));
    unsigned long long K1 = v1
        ? (((unsigned long long)fmono(a1 + b1) << 32) | (unsigned)(4095 - (i1 * 64 + j1)))
        : 0ull;

    unsigned long long last = ~0ull;
    unsigned long long resKey = 0ull;
#pragma unroll
    for (int r = 0; r < 16; r++) {
        unsigned long long m = (K0 < last) ? K0 : 0ull;
        if (K1 < last && K1 > m) m = K1;
#pragma unroll
        for (int off = 16; off >= 1; off >>= 1) {
            unsigned long long o = __shfl_xor_sync(FULLMASK, m, off);
            if (o > m) m = o;
        }
        last = m;
        if (lane == r) resKey = m;
    }

    const int flat = 4095 - (int)((unsigned)resKey & 0xFFFu);
    const int ri = (flat >> 6) & 31;   // valid lanes have ri < 16
    const int rj = flat & 31;          // valid lanes have rj < 16
    const int er = __shfl_sync(FULLMASK, e1v, ri);
    const int ec = __shfl_sync(FULLMASK, e2v, rj);

    if (lane < 16) {
        float fsc = funmono((unsigned)(resKey >> 32));
        // output layout: [global_indices (as exact fp32 values) | final_scores]
        out[(size_t)row * 16 + lane] = (float)(er * 1024 + ec);
        out[(size_t)Rtot * 16 + (size_t)row * 16 + lane] = fsc;
    }
}

// ---------------------------------------------------------------------------
extern "C" void kernel_launch(void* const* d_in, const int* in_sizes, int n_in,
                              void* d_out, int out_size)
{
    const float* q   = (const float*)d_in[0];
    const float* ck  = (const float*)d_in[1];
    const float* cpk = (const float*)d_in[2];
    const float* gm  = (const float*)d_in[3];
    const float* bt  = (const float*)d_in[4];

    const int R = in_sizes[0] / D_DIM;  // 65536

    const size_t smem = (size_t)(32 * 256 + 128 * KS_STRIDE) * sizeof(float);
    cudaFuncSetAttribute(pkr_gemm,
                         cudaFuncAttributeMaxDynamicSharedMemorySize, (int)smem);

    pkr_gemm<<<R / 32, 256, smem>>>(q, ck, cpk, gm, bt);
    pkr_select<<<(R + 7) / 8, 256>>>((float*)d_out, R);
}

// round 5
// speedup vs baseline: 1.8212x; 1.8212x over previous
#include <cuda_runtime.h>
#include <cstdint>

#define FULLMASK 0xffffffffu
#define R_TOT 65536

// ---------------- device scratch (no allocs allowed) ----------------
__device__ float g_scores[(size_t)R_TOT * 2048];   // 512MB
// q_norm, transposed per 128-row block: [b][half][k 0..127][row&127]
__device__ float g_qnT[(size_t)R_TOT * 256];       // 64MB
// keys, permuted for conflict-free staged loads: [half][nb][k][256 perm]
__device__ float g_ktp[2 * 4 * 128 * 256];         // 1MB

// Joint candidates: (i+1)*(j+1) <= 16 (dominance argument) -> 50 cells
__constant__ unsigned char c_CI[50] = {
    0,0,0,0,0,0,0,0,0,0,0,0,0,0,0,0, 1,1,1,1,1,1,1,1, 2,2,2,2,2,
    3,3,3,3, 4,4,4, 5,5, 6,6, 7,7, 8,9,10,11,12,13,14,15
};
__constant__ unsigned char c_CJ[50] = {
    0,1,2,3,4,5,6,7,8,9,10,11,12,13,14,15, 0,1,2,3,4,5,6,7, 0,1,2,3,4,
    0,1,2,3, 0,1,2, 0,1, 0,1, 0,1, 0,0,0,0,0,0,0,0
};

__device__ __forceinline__ unsigned fmono(float f) {
    unsigned u = __float_as_uint(f);
    return u ^ (unsigned)(((int)u >> 31) | (int)0x80000000);
}
__device__ __forceinline__ float funmono(unsigned m) {
    return __uint_as_float((m & 0x80000000u) ? (m ^ 0x80000000u) : ~m);
}

// ---------------------------------------------------------------------------
// K1: LayerNorm — BIT-EXACT replica of the Round-1 numerics (8 threads/row,
// same per-thread sum order, same shfl tree, same Newton rsqrt), but the
// normalized values are written TRANSPOSED (k-major per 128-row block).
// ---------------------------------------------------------------------------
__global__ __launch_bounds__(256)
void pkr_ln(const float* __restrict__ query,
            const float* __restrict__ gma,
            const float* __restrict__ bta)
{
    const int tid = threadIdx.x;
    const int r = tid >> 3, g = tid & 7;
    const int row = blockIdx.x * 32 + r;

    const float4* qp = (const float4*)(query + (size_t)row * 256);
    float4 v[8];
    float s = 0.f;
#pragma unroll
    for (int j = 0; j < 8; j++) {
        v[j] = qp[j * 8 + g];
        s += (v[j].x + v[j].y) + (v[j].z + v[j].w);
    }
#pragma unroll
    for (int off = 4; off >= 1; off >>= 1)
        s += __shfl_xor_sync(FULLMASK, s, off, 8);
    const float mu = s * (1.f / 256.f);

    float s2 = 0.f;
#pragma unroll
    for (int j = 0; j < 8; j++) {
        float dx = v[j].x - mu, dy = v[j].y - mu;
        float dz = v[j].z - mu, dw = v[j].w - mu;
        s2 += (dx * dx + dy * dy) + (dz * dz + dw * dw);
    }
#pragma unroll
    for (int off = 4; off >= 1; off >>= 1)
        s2 += __shfl_xor_sync(FULLMASK, s2, off, 8);

    const float varp = s2 * (1.f / 256.f) + 1e-5f;
    float rs = rsqrtf(varp);
    rs = rs * (1.5f - 0.5f * varp * rs * rs);  // Newton refine (as Round 1)

    const size_t bbase = (size_t)(row >> 7) * 32768;  // 2 halves * 16384
    const int rl = row & 127;
#pragma unroll
    for (int j = 0; j < 8; j++) {
        const int c = j * 32 + g * 4;
        float d0 = (v[j].x - mu) * rs * gma[c + 0] + bta[c + 0];
        float d1 = (v[j].y - mu) * rs * gma[c + 1] + bta[c + 1];
        float d2 = (v[j].z - mu) * rs * gma[c + 2] + bta[c + 2];
        float d3 = (v[j].w - mu) * rs * gma[c + 3] + bta[c + 3];
        float dv[4] = {d0, d1, d2, d3};
#pragma unroll
        for (int i = 0; i < 4; i++) {
            const int ci = c + i;
            const int half = ci >> 7, kl = ci & 127;
            g_qnT[bbase + (size_t)half * 16384 + kl * 128 + rl] = dv[i];
        }
    }
}

// ---------------------------------------------------------------------------
// K2: keys pre-permute: g_ktp[half][nb][k][p] where p=(s*4+e),
// s = cl*16 + tx  <->  global col-chunk (4*tx + cl) within the 256-col tile.
// Makes both GEMM staging and inner-loop LDS fully contiguous.
// ---------------------------------------------------------------------------
__global__ void pkr_kprep(const float* __restrict__ ck, const float* __restrict__ cp)
{
    const int o = blockIdx.x * 256 + threadIdx.x;    // 0..262143
    const int half = o >> 17;
    const int nb = (o >> 15) & 3;
    const int k  = (o >> 8) & 127;
    const int p  = o & 255;
    const int s4 = p >> 2, e = p & 3;
    const int tx = s4 & 15, cl = s4 >> 4;
    const int col = nb * 256 + (4 * tx + cl) * 4 + e;
    const float* src = half ? cp : ck;
    g_ktp[o] = src[(size_t)col * 128 + k];
}

// ---------------------------------------------------------------------------
// K3: fp32x2 packed-FMA GEMM. BM=128, BN=256, 256 threads, 8r x 16c / thread.
// Strictly sequential-k fp32 accumulation per output (bit-exact vs Round 1
// and matching the reference's sequential contraction order).
// ---------------------------------------------------------------------------
#define FMA2(d, a, b) \
    asm("fma.rn.f32x2 %0, %1, %2, %0;" : "+l"(d) : "l"(a), "l"(b))
#define PACK2(d, x) \
    asm("mov.b64 %0, {%1, %1};" : "=l"(d) : "f"(x))

__global__ __launch_bounds__(256, 1)
void pkr_gemm(void)
{
    extern __shared__ float smem[];
    float* qs = smem;            // [128 k][128 rows]  64KB
    float* ks = smem + 16384;    // [128 k][256 perm]  128KB

    const int tid = threadIdx.x;
    const int ty = tid >> 4;     // 0..15 -> rows ty*8..+7
    const int tx = tid & 15;     // col group
    const int b = blockIdx.x;
    const int rowBase = b * 128;

    for (int half = 0; half < 2; half++) {
        __syncthreads();
        {
            const float4* src = (const float4*)(g_qnT + ((size_t)b * 2 + half) * 16384);
            for (int i = tid; i < 4096; i += 256) ((float4*)qs)[i] = src[i];
        }
        for (int nb = 0; nb < 4; nb++) {
            __syncthreads();
            {
                const float4* src = (const float4*)(g_ktp + (size_t)(half * 4 + nb) * 32768);
                for (int i = tid; i < 8192; i += 256) ((float4*)ks)[i] = src[i];
            }
            __syncthreads();

            unsigned long long acc[8][4][2];
#pragma unroll
            for (int r = 0; r < 8; r++)
#pragma unroll
                for (int cl = 0; cl < 4; cl++) {
                    acc[r][cl][0] = 0ull;
                    acc[r][cl][1] = 0ull;
                }

            const float* qrow = qs + ty * 8;
            const float* krow = ks + tx * 4;

#pragma unroll 2
            for (int k = 0; k < 128; k++) {
                float4 qa = *(const float4*)(qrow + k * 128);
                float4 qb = *(const float4*)(qrow + k * 128 + 4);
                unsigned long long qd[8];
                PACK2(qd[0], qa.x); PACK2(qd[1], qa.y);
                PACK2(qd[2], qa.z); PACK2(qd[3], qa.w);
                PACK2(qd[4], qb.x); PACK2(qd[5], qb.y);
                PACK2(qd[6], qb.z); PACK2(qd[7], qb.w);
#pragma unroll
                for (int cl = 0; cl < 4; cl++) {
                    union { float4 f; unsigned long long u[2]; } kv;
                    kv.f = *(const float4*)(krow + k * 256 + cl * 64);
#pragma unroll
                    for (int r = 0; r < 8; r++) {
                        FMA2(acc[r][cl][0], qd[r], kv.u[0]);
                        FMA2(acc[r][cl][1], qd[r], kv.u[1]);
                    }
                }
            }

            // epilogue
#pragma unroll
            for (int r = 0; r < 8; r++) {
                const int row = rowBase + ty * 8 + r;
#pragma unroll
                for (int cl = 0; cl < 4; cl++) {
                    union { float4 f; unsigned long long u[2]; } o;
                    o.u[0] = acc[r][cl][0];
                    o.u[1] = acc[r][cl][1];
                    const int col = half * 1024 + nb * 256 + (4 * tx + cl) * 4;
                    *(float4*)(g_scores + (size_t)row * 2048 + col) = o.f;
                }
            }
        }
    }
}

// ---------------------------------------------------------------------------
// K4: selection. 2 warps per row (one per half) -> exact top-16 per half
// (desc score, asc index), then 50-candidate joint top-16.
// ---------------------------------------------------------------------------
__global__ __launch_bounds__(256)
void pkr_select(float* __restrict__ out, int Rtot)
{
    __shared__ unsigned long long smK[4][2][16];

    const int lane = threadIdx.x & 31;
    const int warp = threadIdx.x >> 5;
    const int r4   = warp >> 1;
    const int half = warp & 1;
    const int row  = blockIdx.x * 4 + r4;

    const float4* bp = (const float4*)(g_scores + (size_t)row * 2048 + half * 1024);
    float4 sv[8];
#pragma unroll
    for (int q2 = 0; q2 < 8; q2++) sv[q2] = bp[q2 * 32 + lane];

    float vmax = -3.4e38f;
#pragma unroll
    for (int q2 = 0; q2 < 8; q2++)
        vmax = fmaxf(vmax, fmaxf(fmaxf(sv[q2].x, sv[q2].y), fmaxf(sv[q2].z, sv[q2].w)));
    // T0 = min over 16 disjoint lane-pairs of pair-max  (<= true rank-16 score)
    float pm = fmaxf(vmax, __shfl_xor_sync(FULLMASK, vmax, 1));
#pragma unroll
    for (int off = 2; off <= 16; off <<= 1)
        pm = fminf(pm, __shfl_xor_sync(FULLMASK, pm, off));
    const float T0f = pm;

    unsigned long long rk = 0ull;
    float Tf = T0f;
    const int lbase = 1023 - lane * 4;

#pragma unroll
    for (int q2 = 0; q2 < 8; q2++) {
        const float* vv = (const float*)&sv[q2];
#pragma unroll
        for (int t = 0; t < 4; t++) {
            const float v = vv[t];
            const bool p = (v >= Tf);
            unsigned long long K = ((unsigned long long)fmono(v) << 32)
                                 | (unsigned)(lbase - q2 * 128 - t);
            unsigned bal = __ballot_sync(FULLMASK, p);
            while (bal) {
                const int src = __ffs(bal) - 1;
                bal &= bal - 1;
                const unsigned long long Kc = __shfl_sync(FULLMASK, K, src);
                const unsigned mg = __ballot_sync(FULLMASK, (lane < 16) && (Kc > rk));
                if (mg) {
                    const int pos = __ffs(mg) - 1;
                    const unsigned long long up = __shfl_up_sync(FULLMASK, rk, 1);
                    if (lane >= pos && lane < 16) rk = (lane == pos) ? Kc : up;
                }
                const unsigned long long T16 = __shfl_sync(FULLMASK, rk, 15);
                Tf = fmaxf(T0f, funmono((unsigned)(T16 >> 32)));
            }
        }
    }
    if (lane < 16) smK[r4][half][lane] = rk;
    __syncthreads();

    if (warp < 4) {
        const int jr = warp;
        const unsigned long long k1 = smK[jr][0][lane & 15];
        const unsigned long long k2 = smK[jr][1][lane & 15];
        const float s1c = funmono((unsigned)(k1 >> 32));
        const float s2c = funmono((unsigned)(k2 >> 32));
        const int e1v = 1023 - (int)(unsigned)k1;
        const int e2v = 1023 - (int)(unsigned)k2;
        const int jrow = blockIdx.x * 4 + jr;

        const int i0 = c_CI[lane], j0 = c_CJ[lane];
        const int cid1 = lane + 32;
        const bool v1 = (cid1 < 50);
        const int i1 = c_CI[v1 ? cid1 : 0], j1 = c_CJ[v1 ? cid1 : 0];

        const float a0 = __shfl_sync(FULLMASK, s1c, i0);
        const float b0 = __shfl_sync(FULLMASK, s2c, j0);
        const float a1 = __shfl_sync(FULLMASK, s1c, i1);
        const float b1 = __shfl_sync(FULLMASK, s2c, j1);

        unsigned long long K0 =
            ((unsigned long long)fmono(a0 + b0) << 32) | (unsigned)(4095 - (i0 * 64 + j0));
        unsigned long long K1 = v1
            ? (((unsigned long long)fmono(a1 + b1) << 32) | (unsigned)(4095 - (i1 * 64 + j1)))
            : 0ull;

        unsigned long long last = ~0ull;
        unsigned long long resKey = 0ull;
#pragma unroll
        for (int r = 0; r < 16; r++) {
            unsigned long long m = (K0 < last) ? K0 : 0ull;
            if (K1 < last && K1 > m) m = K1;
#pragma unroll
            for (int off = 16; off >= 1; off >>= 1) {
                const unsigned long long o = __shfl_xor_sync(FULLMASK, m, off);
                if (o > m) m = o;
            }
            last = m;
            if (lane == r) resKey = m;
        }

        const int flat = 4095 - (int)((unsigned)resKey & 0xFFFu);
        const int ri = (flat >> 6) & 31;
        const int rj = flat & 31;
        const int er = __shfl_sync(FULLMASK, e1v, ri);
        const int ec = __shfl_sync(FULLMASK, e2v, rj);

        if (lane < 16) {
            out[(size_t)jrow * 16 + lane] = (float)(er * 1024 + ec);
            out[(size_t)Rtot * 16 + (size_t)jrow * 16 + lane] =
                funmono((unsigned)(resKey >> 32));
        }
    }
}

// ---------------------------------------------------------------------------
extern "C" void kernel_launch(void* const* d_in, const int* in_sizes, int n_in,
                              void* d_out, int out_size)
{
    const float* q   = (const float*)d_in[0];
    const float* ck  = (const float*)d_in[1];
    const float* cpk = (const float*)d_in[2];
    const float* gm  = (const float*)d_in[3];
    const float* bt  = (const float*)d_in[4];

    const int R = in_sizes[0] / 256;  // 65536

    cudaFuncSetAttribute(pkr_gemm, cudaFuncAttributeMaxDynamicSharedMemorySize, 196608);

    pkr_ln<<<R / 32, 256>>>(q, gm, bt);
    pkr_kprep<<<1024, 256>>>(ck, cpk);
    pkr_gemm<<<R / 128, 256, 196608>>>();
    pkr_select<<<R / 4, 256>>>((float*)d_out, R);
}